// round 8
// baseline (speedup 1.0000x reference)
#include <cuda_runtime.h>
#include <cstdint>
#include <math.h>

#define BB 32
#define VV 50
#define EE 2450
#define NBV 1600

__device__ float g_P[(size_t)NBV * 1536];             // k1 out; later k4 scratch (5 x 409600)
__device__ float g_msg3[(size_t)3 * BB * EE * 256];   // per-type messages
__device__ float g_agg[(size_t)NBV * 256];

extern __shared__ char s_dyn[];

// ===================== helpers =====================
__device__ __forceinline__ float ftanh(float x) {
    float y; asm("tanh.approx.f32 %0, %1;" : "=f"(y) : "f"(x)); return y;
}
__device__ __forceinline__ uint32_t to_tf32(float x) {
    uint32_t u; asm("cvt.rna.tf32.f32 %0, %1;" : "=r"(u) : "f"(x)); return u;
}
__device__ __forceinline__ void mma1688(float d[4],
                                        uint32_t a0, uint32_t a1, uint32_t a2, uint32_t a3,
                                        uint32_t b0, uint32_t b1) {
    asm volatile(
        "mma.sync.aligned.m16n8k8.row.col.f32.tf32.tf32.f32 "
        "{%0,%1,%2,%3}, {%4,%5,%6,%7}, {%8,%9}, {%0,%1,%2,%3};"
        : "+f"(d[0]), "+f"(d[1]), "+f"(d[2]), "+f"(d[3])
        : "r"(a0), "r"(a1), "r"(a2), "r"(a3), "r"(b0), "r"(b1));
}
#define APAD 36

// ===================== K2: per-type tf32 message kernel =====================
// block = 128 edges x 256 cols x 1 type. grid (20, 32, 3). 8 warps 2m x 4n (warp 64x64).
#define K2_SMEM ((128 + 256) * APAD * 4 + (128 + 256) * 4)
__global__ void __launch_bounds__(256, 1)
k2_msg(const float* __restrict__ edges, const float* __restrict__ W2,
       const float* __restrict__ b2) {
    char* sm = s_dyn;
    uint32_t (*As)[APAD] = (uint32_t(*)[APAD])sm;                       // [128][36]
    uint32_t (*Bs)[APAD] = (uint32_t(*)[APAD])(sm + 128 * APAD * 4);    // [256][36]
    float* sEw = (float*)(sm + (128 + 256) * APAD * 4);                 // [128]
    float* sB2 = sEw + 128;                                             // [256]

    const int tid = threadIdx.x;
    const int wid = tid >> 5, lane = tid & 31;
    const int gid = lane >> 2, tig = lane & 3;
    const int wn = wid & 3, wm = wid >> 2;     // 2(m) x 4(n)
    const int e0 = blockIdx.x * 128;
    const int b  = blockIdx.y;
    const int t  = blockIdx.z;

    if (tid < 128) {
        int e = e0 + tid;
        sEw[tid] = (e < EE) ? edges[((size_t)b * EE + e) * 4 + 1 + t] : 0.f;
    }
    sB2[tid] = b2[t * 256 + tid];

    float acc[4][8][4];
#pragma unroll
    for (int mt = 0; mt < 4; mt++)
#pragma unroll
        for (int nt = 0; nt < 8; nt++)
#pragma unroll
            for (int c = 0; c < 4; c++) acc[mt][nt][c] = 0.f;

    const float* Pbase = g_P + (size_t)(t * 2) * 256;

    for (int kc = 0; kc < 256; kc += 32) {
        __syncthreads();   // frag loads of previous iter done
        // ---- A build: h1 = tanh(Pr + Ps) tf32, 128 x 32 ----
#pragma unroll
        for (int i = tid; i < 1024; i += 256) {
            int row = i >> 3, k0 = (i & 7) * 4;
            int e = e0 + row;
            uint4 u = {0u, 0u, 0u, 0u};
            if (e < EE) {
                int s = e / 49, j = e - s * 49;
                int vr = j + (j >= s);
                float4 pr = *(const float4*)(Pbase + (size_t)(b * VV + vr) * 1536 + kc + k0);
                float4 ps = *(const float4*)(Pbase + (size_t)(b * VV + s) * 1536 + 256 + kc + k0);
                u.x = to_tf32(ftanh(pr.x + ps.x));
                u.y = to_tf32(ftanh(pr.y + ps.y));
                u.z = to_tf32(ftanh(pr.z + ps.z));
                u.w = to_tf32(ftanh(pr.w + ps.w));
            }
            *(uint4*)&As[row][k0] = u;
        }
        // ---- B build: W2 slice tf32, 256 x 32 ----
#pragma unroll
        for (int i = tid; i < 2048; i += 256) {
            int n = i >> 3, k0 = (i & 7) * 4;
            float4 w = *(const float4*)(W2 + ((size_t)t * 256 + n) * 256 + kc + k0);
            uint4 u;
            u.x = to_tf32(w.x); u.y = to_tf32(w.y); u.z = to_tf32(w.z); u.w = to_tf32(w.w);
            *(uint4*)&Bs[n][k0] = u;
        }
        __syncthreads();
#pragma unroll
        for (int ks = 0; ks < 4; ks++) {
            int k = ks * 8;
            uint32_t a[4][4];
#pragma unroll
            for (int mt = 0; mt < 4; mt++) {
                int row = wm * 64 + mt * 16 + gid;
                a[mt][0] = As[row][k + tig];
                a[mt][1] = As[row + 8][k + tig];
                a[mt][2] = As[row][k + tig + 4];
                a[mt][3] = As[row + 8][k + tig + 4];
            }
#pragma unroll
            for (int nt = 0; nt < 8; nt++) {
                int n = wn * 64 + nt * 8 + gid;
                uint32_t b0 = Bs[n][k + tig];
                uint32_t b1 = Bs[n][k + tig + 4];
#pragma unroll
                for (int mt = 0; mt < 4; mt++)
                    mma1688(acc[mt][nt], a[mt][0], a[mt][1], a[mt][2], a[mt][3], b0, b1);
            }
        }
    }
    // ---- epilogue: msg = tanh(acc + b2) * ew, store to per-type buffer ----
    float* mout = g_msg3 + ((size_t)t * BB + b) * EE * 256;
#pragma unroll
    for (int mt = 0; mt < 4; mt++) {
        int rl = wm * 64 + mt * 16 + gid;
        int eA = e0 + rl, eB = eA + 8;
        float ewA = sEw[rl], ewB = sEw[rl + 8];
#pragma unroll
        for (int nt = 0; nt < 8; nt++) {
            int c0 = wn * 64 + nt * 8 + 2 * tig;
            float bb0 = sB2[c0], bb1 = sB2[c0 + 1];
            if (eA < EE)
                *(float2*)(mout + (size_t)eA * 256 + c0) =
                    make_float2(ftanh(acc[mt][nt][0] + bb0) * ewA,
                                ftanh(acc[mt][nt][1] + bb1) * ewA);
            if (eB < EE)
                *(float2*)(mout + (size_t)eB * 256 + c0) =
                    make_float2(ftanh(acc[mt][nt][2] + bb0) * ewB,
                                ftanh(acc[mt][nt][3] + bb1) * ewB);
        }
    }
}

// ===================== K3: aggregate over incoming edges + types =====================
__global__ void k3_agg() {
    const int bv = blockIdx.x;
    const int b = bv / VV, v = bv - b * VV;
    const int h = threadIdx.x;
    const size_t toff = (size_t)BB * EE * 256;
    const float* base = g_msg3 + (size_t)b * EE * 256;
    float s0 = 0.f, s1 = 0.f, s2 = 0.f;
    for (int snd = 0; snd < VV; ++snd) {
        if (snd == v) continue;
        int j = (v < snd) ? v : v - 1;
        size_t off = (size_t)(snd * 49 + j) * 256 + h;
        s0 += base[off];
        s1 += base[toff + off];
        s2 += base[2 * toff + off];
    }
    g_agg[(size_t)bv * 256 + h] = (s0 + s1 + s2) * (1.f / 147.f);
}

// ===================== generic tf32 mma GEMM: C = act(A @ W^T + bias) =====================
// block tile 128 x 128, 8 warps 2m x 4n (warp 64 x 32). per-z args.
struct GArg {
    const float* A;        // [M, 256]
    const float* W;        // rows at stride wld
    const float* bias;     // [128*gridDim.y] or null
    float* out;
    int wld, outld, outcol, act;
};
struct GArgs { GArg g[6]; };

__global__ void __launch_bounds__(256, 2)
kg_mma(GArgs args, int M) {
    __shared__ uint32_t As[128][APAD];
    __shared__ uint32_t Bs[128][APAD];
    const GArg ga = args.g[blockIdx.z];
    const int tid = threadIdx.x;
    const int wid = tid >> 5, lane = tid & 31;
    const int gid = lane >> 2, tig = lane & 3;
    const int wn = wid & 3, wm = wid >> 2;     // 2(m) x 4(n), warp 64x32
    const int row0 = blockIdx.x * 128;
    const int col0 = blockIdx.y * 128;

    float acc[4][4][4];
#pragma unroll
    for (int mt = 0; mt < 4; mt++)
#pragma unroll
        for (int nt = 0; nt < 4; nt++)
#pragma unroll
            for (int c = 0; c < 4; c++) acc[mt][nt][c] = 0.f;

    for (int kc = 0; kc < 256; kc += 32) {
        __syncthreads();
#pragma unroll
        for (int i = tid; i < 1024; i += 256) {
            int r = i >> 3, k0 = (i & 7) * 4;
            int row = row0 + r;
            uint4 u = {0u, 0u, 0u, 0u};
            if (row < M) {
                float4 a = *(const float4*)(ga.A + (size_t)row * 256 + kc + k0);
                u.x = to_tf32(a.x); u.y = to_tf32(a.y); u.z = to_tf32(a.z); u.w = to_tf32(a.w);
            }
            *(uint4*)&As[r][k0] = u;
        }
#pragma unroll
        for (int i = tid; i < 1024; i += 256) {
            int n = i >> 3, k0 = (i & 7) * 4;
            float4 w = *(const float4*)(ga.W + (size_t)(col0 + n) * ga.wld + kc + k0);
            uint4 u;
            u.x = to_tf32(w.x); u.y = to_tf32(w.y); u.z = to_tf32(w.z); u.w = to_tf32(w.w);
            *(uint4*)&Bs[n][k0] = u;
        }
        __syncthreads();
#pragma unroll
        for (int ks = 0; ks < 4; ks++) {
            int k = ks * 8;
            uint32_t a[4][4];
#pragma unroll
            for (int mt = 0; mt < 4; mt++) {
                int row = wm * 64 + mt * 16 + gid;
                a[mt][0] = As[row][k + tig];
                a[mt][1] = As[row + 8][k + tig];
                a[mt][2] = As[row][k + tig + 4];
                a[mt][3] = As[row + 8][k + tig + 4];
            }
#pragma unroll
            for (int nt = 0; nt < 4; nt++) {
                int n = wn * 32 + nt * 8 + gid;
                uint32_t b0 = Bs[n][k + tig];
                uint32_t b1 = Bs[n][k + tig + 4];
#pragma unroll
                for (int mt = 0; mt < 4; mt++)
                    mma1688(acc[mt][nt], a[mt][0], a[mt][1], a[mt][2], a[mt][3], b0, b1);
            }
        }
    }
#pragma unroll
    for (int mt = 0; mt < 4; mt++) {
        int rl = wm * 64 + mt * 16 + gid;
        int rA = row0 + rl, rB = rA + 8;
#pragma unroll
        for (int nt = 0; nt < 4; nt++) {
            int c0 = wn * 32 + nt * 8 + 2 * tig;
            float bb0 = 0.f, bb1 = 0.f;
            if (ga.bias) { bb0 = ga.bias[col0 + c0]; bb1 = ga.bias[col0 + c0 + 1]; }
            float v0 = acc[mt][nt][0] + bb0, v1 = acc[mt][nt][1] + bb1;
            float v2 = acc[mt][nt][2] + bb0, v3 = acc[mt][nt][3] + bb1;
            if (ga.act) {
                v0 = fmaxf(v0, 0.f); v1 = fmaxf(v1, 0.f);
                v2 = fmaxf(v2, 0.f); v3 = fmaxf(v3, 0.f);
            }
            int gc = ga.outcol + col0 + c0;
            if (rA < M) *(float2*)(ga.out + (size_t)rA * ga.outld + gc) = make_float2(v0, v1);
            if (rB < M) *(float2*)(ga.out + (size_t)rB * ga.outld + gc) = make_float2(v2, v3);
        }
    }
}

// ===================== gates =====================
__global__ void kgate(const float* __restrict__ inputs, const float* __restrict__ hidden,
                      const float* __restrict__ SR, const float* __restrict__ SI,
                      const float* __restrict__ SN,
                      const float* __restrict__ Wir, const float* __restrict__ bir,
                      const float* __restrict__ Wii, const float* __restrict__ bii,
                      const float* __restrict__ Win, const float* __restrict__ binw,
                      float* __restrict__ out) {
    const int row = blockIdx.x, col = threadIdx.x;
    __shared__ float x[6];
    if (col < 6) x[col] = inputs[row * 6 + col];
    __syncthreads();
    float xr = bir[col], xi = bii[col], xn = binw[col];
#pragma unroll
    for (int d = 0; d < 6; d++) {
        float xd = x[d];
        xr += Wir[col*6+d] * xd; xi += Wii[col*6+d] * xd; xn += Win[col*6+d] * xd;
    }
    size_t idx = (size_t)row * 256 + col;
    float rg = 1.f / (1.f + expf(-(SR[idx] + xr)));
    float ig = 1.f / (1.f + expf(-(SI[idx] + xi)));
    float ng = tanhf(xn + rg * SN[idx]);
    out[9600 + idx] = (1.f - ig) * ng + ig * hidden[idx];
}

// ===================== prediction =====================
__global__ void kpred(const float* __restrict__ inputs, const float* __restrict__ p2,
                      const float* __restrict__ Wo3, const float* __restrict__ bo3,
                      float* __restrict__ out) {
    __shared__ float sP[32 * 257];
    __shared__ float sW3[6 * 256];
    const int tid = threadIdx.x;
    const int row0 = blockIdx.x * 32;
    for (int i = tid; i < 32 * 256; i += 256) {
        int r = i >> 8, k = i & 255;
        sP[r * 257 + k] = p2[(size_t)(row0 + r) * 256 + k];
    }
    for (int i = tid; i < 1536; i += 256) sW3[i] = Wo3[i];
    __syncthreads();
    if (tid < 192) {
        int row = tid / 6, d = tid - (tid / 6) * 6;
        float s = bo3[d];
        for (int k = 0; k < 256; k++) s += sP[row * 257 + k] * sW3[d * 256 + k];
        size_t g = (size_t)(row0 + row) * 6 + d;
        out[g] = inputs[g] + s;
    }
}

// ===================== launch =====================
extern "C" void kernel_launch(void* const* d_in, const int* in_sizes, int n_in,
                              void* d_out, int out_size) {
    const float* inputs = (const float*)d_in[0];
    const float* hidden = (const float*)d_in[1];
    const float* edges  = (const float*)d_in[2];
    const float* W1     = (const float*)d_in[3];
    const float* b1     = (const float*)d_in[4];
    const float* W2     = (const float*)d_in[5];
    const float* b2     = (const float*)d_in[6];
    const float* Whr    = (const float*)d_in[7];
    const float* Whi    = (const float*)d_in[8];
    const float* Whh    = (const float*)d_in[9];
    const float* Wir    = (const float*)d_in[10];
    const float* bir    = (const float*)d_in[11];
    const float* Wii    = (const float*)d_in[12];
    const float* bii    = (const float*)d_in[13];
    const float* Win    = (const float*)d_in[14];
    const float* binw   = (const float*)d_in[15];
    const float* Wo1    = (const float*)d_in[16];
    const float* bo1    = (const float*)d_in[17];
    const float* Wo2    = (const float*)d_in[18];
    const float* bo2    = (const float*)d_in[19];
    const float* Wo3    = (const float*)d_in[20];
    const float* bo3    = (const float*)d_in[21];
    float* out = (float*)d_out;

    void* pP = nullptr; void* pAgg = nullptr;
    cudaGetSymbolAddress(&pP, g_P);
    cudaGetSymbolAddress(&pAgg, g_agg);
    float* gp = (float*)pP;
    float* gagg = (float*)pAgg;
    float* SR = gp;                 // g_P reused as scratch after k2 consumes it
    float* SI = gp + 409600;
    float* SN = gp + 819200;
    float* P1 = gp + 1228800;
    float* P2 = gp + 1638400;

    cudaFuncSetAttribute(k2_msg, cudaFuncAttributeMaxDynamicSharedMemorySize, K2_SMEM);

    // K1: node projections via mma, z -> (t, dir)
    {
        GArgs a;
        for (int z = 0; z < 6; z++) {
            int t = z >> 1, dir = z & 1;
            a.g[z].A = hidden;
            a.g[z].W = W1 + (size_t)t * 256 * 512 + dir * 256;
            a.g[z].wld = 512;
            a.g[z].bias = (dir == 0) ? (b1 + t * 256) : nullptr;
            a.g[z].out = gp;
            a.g[z].outld = 1536;
            a.g[z].outcol = (t * 2 + dir) * 256;
            a.g[z].act = 0;
        }
        kg_mma<<<dim3(13, 2, 6), 256>>>(a, NBV);
    }
    k2_msg<<<dim3(20, 32, 3), 256, K2_SMEM>>>(edges, W2, b2);
    k3_agg<<<1600, 256>>>();
    // R, I, N
    {
        GArgs a;
        const float* Ws[3] = {Whr, Whi, Whh};
        float* Os[3] = {SR, SI, SN};
        for (int z = 0; z < 3; z++) {
            a.g[z].A = gagg; a.g[z].W = Ws[z]; a.g[z].wld = 256;
            a.g[z].bias = nullptr; a.g[z].out = Os[z];
            a.g[z].outld = 256; a.g[z].outcol = 0; a.g[z].act = 0;
        }
        kg_mma<<<dim3(13, 2, 3), 256>>>(a, NBV);
    }
    kgate<<<1600, 256>>>(inputs, hidden, SR, SI, SN,
                         Wir, bir, Wii, bii, Win, binw, out);
    {
        GArgs a;
        a.g[0].A = out + 9600; a.g[0].W = Wo1; a.g[0].wld = 256;
        a.g[0].bias = bo1; a.g[0].out = P1; a.g[0].outld = 256;
        a.g[0].outcol = 0; a.g[0].act = 1;
        kg_mma<<<dim3(13, 2, 1), 256>>>(a, NBV);
        a.g[0].A = P1; a.g[0].W = Wo2; a.g[0].bias = bo2; a.g[0].out = P2;
        kg_mma<<<dim3(13, 2, 1), 256>>>(a, NBV);
    }
    kpred<<<50, 256>>>(inputs, P2, Wo3, bo3, out);
}

// round 9
// speedup vs baseline: 1.0016x; 1.0016x over previous
#include <cuda_runtime.h>
#include <cstdint>
#include <math.h>

#define BB 32
#define VV 50
#define EE 2450
#define NBV 1600

__device__ float g_P[(size_t)NBV * 1536];             // k1 out; later k4 scratch (5 x 409600)
__device__ float g_msg3[(size_t)3 * BB * EE * 256];   // per-type messages
__device__ float g_agg[(size_t)NBV * 256];

extern __shared__ char s_dyn[];

// ===================== helpers =====================
__device__ __forceinline__ float ftanh(float x) {
    float y; asm("tanh.approx.f32 %0, %1;" : "=f"(y) : "f"(x)); return y;
}
__device__ __forceinline__ uint32_t to_tf32(float x) {
    uint32_t u; asm("cvt.rna.tf32.f32 %0, %1;" : "=r"(u) : "f"(x)); return u;
}
__device__ __forceinline__ void mma1688(float d[4],
                                        uint32_t a0, uint32_t a1, uint32_t a2, uint32_t a3,
                                        uint32_t b0, uint32_t b1) {
    asm volatile(
        "mma.sync.aligned.m16n8k8.row.col.f32.tf32.tf32.f32 "
        "{%0,%1,%2,%3}, {%4,%5,%6,%7}, {%8,%9}, {%0,%1,%2,%3};"
        : "+f"(d[0]), "+f"(d[1]), "+f"(d[2]), "+f"(d[3])
        : "r"(a0), "r"(a1), "r"(a2), "r"(a3), "r"(b0), "r"(b1));
}
#define APAD 36

// ===================== K2: per-type tf32 message kernel =====================
// block = 128 edges x 256 cols x 1 type. grid (20, 32, 3). 8 warps 2m x 4n (warp 64x64).
#define K2_SMEM ((128 + 256) * APAD * 4 + (128 + 256) * 4)
__global__ void __launch_bounds__(256, 1)
k2_msg(const float* __restrict__ edges, const float* __restrict__ W2,
       const float* __restrict__ b2) {
    char* sm = s_dyn;
    uint32_t (*As)[APAD] = (uint32_t(*)[APAD])sm;                       // [128][36]
    uint32_t (*Bs)[APAD] = (uint32_t(*)[APAD])(sm + 128 * APAD * 4);    // [256][36]
    float* sEw = (float*)(sm + (128 + 256) * APAD * 4);                 // [128]
    float* sB2 = sEw + 128;                                             // [256]

    const int tid = threadIdx.x;
    const int wid = tid >> 5, lane = tid & 31;
    const int gid = lane >> 2, tig = lane & 3;
    const int wn = wid & 3, wm = wid >> 2;     // 2(m) x 4(n)
    const int e0 = blockIdx.x * 128;
    const int b  = blockIdx.y;
    const int t  = blockIdx.z;

    if (tid < 128) {
        int e = e0 + tid;
        sEw[tid] = (e < EE) ? edges[((size_t)b * EE + e) * 4 + 1 + t] : 0.f;
    }
    sB2[tid] = b2[t * 256 + tid];

    float acc[4][8][4];
#pragma unroll
    for (int mt = 0; mt < 4; mt++)
#pragma unroll
        for (int nt = 0; nt < 8; nt++)
#pragma unroll
            for (int c = 0; c < 4; c++) acc[mt][nt][c] = 0.f;

    const float* Pbase = g_P + (size_t)(t * 2) * 256;

    for (int kc = 0; kc < 256; kc += 32) {
        __syncthreads();   // frag loads of previous iter done
        // ---- A build: h1 = tanh(Pr + Ps) tf32, 128 x 32 ----
#pragma unroll
        for (int i = tid; i < 1024; i += 256) {
            int row = i >> 3, k0 = (i & 7) * 4;
            int e = e0 + row;
            uint4 u = {0u, 0u, 0u, 0u};
            if (e < EE) {
                int s = e / 49, j = e - s * 49;
                int vr = j + (j >= s);
                float4 pr = *(const float4*)(Pbase + (size_t)(b * VV + vr) * 1536 + kc + k0);
                float4 ps = *(const float4*)(Pbase + (size_t)(b * VV + s) * 1536 + 256 + kc + k0);
                u.x = to_tf32(ftanh(pr.x + ps.x));
                u.y = to_tf32(ftanh(pr.y + ps.y));
                u.z = to_tf32(ftanh(pr.z + ps.z));
                u.w = to_tf32(ftanh(pr.w + ps.w));
            }
            *(uint4*)&As[row][k0] = u;
        }
        // ---- B build: W2 slice tf32, 256 x 32 ----
#pragma unroll
        for (int i = tid; i < 2048; i += 256) {
            int n = i >> 3, k0 = (i & 7) * 4;
            float4 w = *(const float4*)(W2 + ((size_t)t * 256 + n) * 256 + kc + k0);
            uint4 u;
            u.x = to_tf32(w.x); u.y = to_tf32(w.y); u.z = to_tf32(w.z); u.w = to_tf32(w.w);
            *(uint4*)&Bs[n][k0] = u;
        }
        __syncthreads();
#pragma unroll
        for (int ks = 0; ks < 4; ks++) {
            int k = ks * 8;
            uint32_t a[4][4];
#pragma unroll
            for (int mt = 0; mt < 4; mt++) {
                int row = wm * 64 + mt * 16 + gid;
                a[mt][0] = As[row][k + tig];
                a[mt][1] = As[row + 8][k + tig];
                a[mt][2] = As[row][k + tig + 4];
                a[mt][3] = As[row + 8][k + tig + 4];
            }
#pragma unroll
            for (int nt = 0; nt < 8; nt++) {
                int n = wn * 64 + nt * 8 + gid;
                uint32_t b0 = Bs[n][k + tig];
                uint32_t b1 = Bs[n][k + tig + 4];
#pragma unroll
                for (int mt = 0; mt < 4; mt++)
                    mma1688(acc[mt][nt], a[mt][0], a[mt][1], a[mt][2], a[mt][3], b0, b1);
            }
        }
    }
    // ---- epilogue: msg = tanh(acc + b2) * ew, store to per-type buffer ----
    float* mout = g_msg3 + ((size_t)t * BB + b) * EE * 256;
#pragma unroll
    for (int mt = 0; mt < 4; mt++) {
        int rl = wm * 64 + mt * 16 + gid;
        int eA = e0 + rl, eB = eA + 8;
        float ewA = sEw[rl], ewB = sEw[rl + 8];
#pragma unroll
        for (int nt = 0; nt < 8; nt++) {
            int c0 = wn * 64 + nt * 8 + 2 * tig;
            float bb0 = sB2[c0], bb1 = sB2[c0 + 1];
            if (eA < EE)
                *(float2*)(mout + (size_t)eA * 256 + c0) =
                    make_float2(ftanh(acc[mt][nt][0] + bb0) * ewA,
                                ftanh(acc[mt][nt][1] + bb1) * ewA);
            if (eB < EE)
                *(float2*)(mout + (size_t)eB * 256 + c0) =
                    make_float2(ftanh(acc[mt][nt][2] + bb0) * ewB,
                                ftanh(acc[mt][nt][3] + bb1) * ewB);
        }
    }
}

// ===================== K3: aggregate over incoming edges + types =====================
__global__ void k3_agg() {
    const int bv = blockIdx.x;
    const int b = bv / VV, v = bv - b * VV;
    const int h = threadIdx.x;
    const size_t toff = (size_t)BB * EE * 256;
    const float* base = g_msg3 + (size_t)b * EE * 256;
    float s0 = 0.f, s1 = 0.f, s2 = 0.f;
    for (int snd = 0; snd < VV; ++snd) {
        if (snd == v) continue;
        int j = (v < snd) ? v : v - 1;
        size_t off = (size_t)(snd * 49 + j) * 256 + h;
        s0 += base[off];
        s1 += base[toff + off];
        s2 += base[2 * toff + off];
    }
    g_agg[(size_t)bv * 256 + h] = (s0 + s1 + s2) * (1.f / 147.f);
}

// ===================== generic tf32 mma GEMM: C = act(A @ W^T + bias) =====================
// block tile 128 x 128, 8 warps 2m x 4n (warp 64 x 32). per-z args.
struct GArg {
    const float* A;        // [M, 256]
    const float* W;        // rows at stride wld
    const float* bias;     // [128*gridDim.y] or null
    float* out;
    int wld, outld, outcol, act;
};
struct GArgs { GArg g[6]; };

__global__ void __launch_bounds__(256, 2)
kg_mma(GArgs args, int M) {
    __shared__ uint32_t As[128][APAD];
    __shared__ uint32_t Bs[128][APAD];
    const GArg ga = args.g[blockIdx.z];
    const int tid = threadIdx.x;
    const int wid = tid >> 5, lane = tid & 31;
    const int gid = lane >> 2, tig = lane & 3;
    const int wn = wid & 3, wm = wid >> 2;     // 2(m) x 4(n), warp 64x32
    const int row0 = blockIdx.x * 128;
    const int col0 = blockIdx.y * 128;

    float acc[4][4][4];
#pragma unroll
    for (int mt = 0; mt < 4; mt++)
#pragma unroll
        for (int nt = 0; nt < 4; nt++)
#pragma unroll
            for (int c = 0; c < 4; c++) acc[mt][nt][c] = 0.f;

    for (int kc = 0; kc < 256; kc += 32) {
        __syncthreads();
#pragma unroll
        for (int i = tid; i < 1024; i += 256) {
            int r = i >> 3, k0 = (i & 7) * 4;
            int row = row0 + r;
            uint4 u = {0u, 0u, 0u, 0u};
            if (row < M) {
                float4 a = *(const float4*)(ga.A + (size_t)row * 256 + kc + k0);
                u.x = to_tf32(a.x); u.y = to_tf32(a.y); u.z = to_tf32(a.z); u.w = to_tf32(a.w);
            }
            *(uint4*)&As[r][k0] = u;
        }
#pragma unroll
        for (int i = tid; i < 1024; i += 256) {
            int n = i >> 3, k0 = (i & 7) * 4;
            float4 w = *(const float4*)(ga.W + (size_t)(col0 + n) * ga.wld + kc + k0);
            uint4 u;
            u.x = to_tf32(w.x); u.y = to_tf32(w.y); u.z = to_tf32(w.z); u.w = to_tf32(w.w);
            *(uint4*)&Bs[n][k0] = u;
        }
        __syncthreads();
#pragma unroll
        for (int ks = 0; ks < 4; ks++) {
            int k = ks * 8;
            uint32_t a[4][4];
#pragma unroll
            for (int mt = 0; mt < 4; mt++) {
                int row = wm * 64 + mt * 16 + gid;
                a[mt][0] = As[row][k + tig];
                a[mt][1] = As[row + 8][k + tig];
                a[mt][2] = As[row][k + tig + 4];
                a[mt][3] = As[row + 8][k + tig + 4];
            }
#pragma unroll
            for (int nt = 0; nt < 4; nt++) {
                int n = wn * 32 + nt * 8 + gid;
                uint32_t b0 = Bs[n][k + tig];
                uint32_t b1 = Bs[n][k + tig + 4];
#pragma unroll
                for (int mt = 0; mt < 4; mt++)
                    mma1688(acc[mt][nt], a[mt][0], a[mt][1], a[mt][2], a[mt][3], b0, b1);
            }
        }
    }
#pragma unroll
    for (int mt = 0; mt < 4; mt++) {
        int rl = wm * 64 + mt * 16 + gid;
        int rA = row0 + rl, rB = rA + 8;
#pragma unroll
        for (int nt = 0; nt < 4; nt++) {
            int c0 = wn * 32 + nt * 8 + 2 * tig;
            float bb0 = 0.f, bb1 = 0.f;
            if (ga.bias) { bb0 = ga.bias[col0 + c0]; bb1 = ga.bias[col0 + c0 + 1]; }
            float v0 = acc[mt][nt][0] + bb0, v1 = acc[mt][nt][1] + bb1;
            float v2 = acc[mt][nt][2] + bb0, v3 = acc[mt][nt][3] + bb1;
            if (ga.act) {
                v0 = fmaxf(v0, 0.f); v1 = fmaxf(v1, 0.f);
                v2 = fmaxf(v2, 0.f); v3 = fmaxf(v3, 0.f);
            }
            int gc = ga.outcol + col0 + c0;
            if (rA < M) *(float2*)(ga.out + (size_t)rA * ga.outld + gc) = make_float2(v0, v1);
            if (rB < M) *(float2*)(ga.out + (size_t)rB * ga.outld + gc) = make_float2(v2, v3);
        }
    }
}

// ===================== gates =====================
__global__ void kgate(const float* __restrict__ inputs, const float* __restrict__ hidden,
                      const float* __restrict__ SR, const float* __restrict__ SI,
                      const float* __restrict__ SN,
                      const float* __restrict__ Wir, const float* __restrict__ bir,
                      const float* __restrict__ Wii, const float* __restrict__ bii,
                      const float* __restrict__ Win, const float* __restrict__ binw,
                      float* __restrict__ out) {
    const int row = blockIdx.x, col = threadIdx.x;
    __shared__ float x[6];
    if (col < 6) x[col] = inputs[row * 6 + col];
    __syncthreads();
    float xr = bir[col], xi = bii[col], xn = binw[col];
#pragma unroll
    for (int d = 0; d < 6; d++) {
        float xd = x[d];
        xr += Wir[col*6+d] * xd; xi += Wii[col*6+d] * xd; xn += Win[col*6+d] * xd;
    }
    size_t idx = (size_t)row * 256 + col;
    float rg = 1.f / (1.f + expf(-(SR[idx] + xr)));
    float ig = 1.f / (1.f + expf(-(SI[idx] + xi)));
    float ng = tanhf(xn + rg * SN[idx]);
    out[9600 + idx] = (1.f - ig) * ng + ig * hidden[idx];
}

// ===================== prediction =====================
__global__ void kpred(const float* __restrict__ inputs, const float* __restrict__ p2,
                      const float* __restrict__ Wo3, const float* __restrict__ bo3,
                      float* __restrict__ out) {
    __shared__ float sP[32 * 257];
    __shared__ float sW3[6 * 256];
    const int tid = threadIdx.x;
    const int row0 = blockIdx.x * 32;
    for (int i = tid; i < 32 * 256; i += 256) {
        int r = i >> 8, k = i & 255;
        sP[r * 257 + k] = p2[(size_t)(row0 + r) * 256 + k];
    }
    for (int i = tid; i < 1536; i += 256) sW3[i] = Wo3[i];
    __syncthreads();
    if (tid < 192) {
        int row = tid / 6, d = tid - (tid / 6) * 6;
        float s = bo3[d];
        for (int k = 0; k < 256; k++) s += sP[row * 257 + k] * sW3[d * 256 + k];
        size_t g = (size_t)(row0 + row) * 6 + d;
        out[g] = inputs[g] + s;
    }
}

// ===================== launch =====================
extern "C" void kernel_launch(void* const* d_in, const int* in_sizes, int n_in,
                              void* d_out, int out_size) {
    const float* inputs = (const float*)d_in[0];
    const float* hidden = (const float*)d_in[1];
    const float* edges  = (const float*)d_in[2];
    const float* W1     = (const float*)d_in[3];
    const float* b1     = (const float*)d_in[4];
    const float* W2     = (const float*)d_in[5];
    const float* b2     = (const float*)d_in[6];
    const float* Whr    = (const float*)d_in[7];
    const float* Whi    = (const float*)d_in[8];
    const float* Whh    = (const float*)d_in[9];
    const float* Wir    = (const float*)d_in[10];
    const float* bir    = (const float*)d_in[11];
    const float* Wii    = (const float*)d_in[12];
    const float* bii    = (const float*)d_in[13];
    const float* Win    = (const float*)d_in[14];
    const float* binw   = (const float*)d_in[15];
    const float* Wo1    = (const float*)d_in[16];
    const float* bo1    = (const float*)d_in[17];
    const float* Wo2    = (const float*)d_in[18];
    const float* bo2    = (const float*)d_in[19];
    const float* Wo3    = (const float*)d_in[20];
    const float* bo3    = (const float*)d_in[21];
    float* out = (float*)d_out;

    void* pP = nullptr; void* pAgg = nullptr;
    cudaGetSymbolAddress(&pP, g_P);
    cudaGetSymbolAddress(&pAgg, g_agg);
    float* gp = (float*)pP;
    float* gagg = (float*)pAgg;
    float* SR = gp;                 // g_P reused as scratch after k2 consumes it
    float* SI = gp + 409600;
    float* SN = gp + 819200;
    float* P1 = gp + 1228800;
    float* P2 = gp + 1638400;

    cudaFuncSetAttribute(k2_msg, cudaFuncAttributeMaxDynamicSharedMemorySize, K2_SMEM);

    // K1: node projections via mma, z -> (t, dir)
    {
        GArgs a;
        for (int z = 0; z < 6; z++) {
            int t = z >> 1, dir = z & 1;
            a.g[z].A = hidden;
            a.g[z].W = W1 + (size_t)t * 256 * 512 + dir * 256;
            a.g[z].wld = 512;
            a.g[z].bias = (dir == 0) ? (b1 + t * 256) : nullptr;
            a.g[z].out = gp;
            a.g[z].outld = 1536;
            a.g[z].outcol = (t * 2 + dir) * 256;
            a.g[z].act = 0;
        }
        kg_mma<<<dim3(13, 2, 6), 256>>>(a, NBV);
    }
    k2_msg<<<dim3(20, 32, 3), 256, K2_SMEM>>>(edges, W2, b2);
    k3_agg<<<1600, 256>>>();
    // R, I, N
    {
        GArgs a;
        const float* Ws[3] = {Whr, Whi, Whh};
        float* Os[3] = {SR, SI, SN};
        for (int z = 0; z < 3; z++) {
            a.g[z].A = gagg; a.g[z].W = Ws[z]; a.g[z].wld = 256;
            a.g[z].bias = nullptr; a.g[z].out = Os[z];
            a.g[z].outld = 256; a.g[z].outcol = 0; a.g[z].act = 0;
        }
        kg_mma<<<dim3(13, 2, 3), 256>>>(a, NBV);
    }
    kgate<<<1600, 256>>>(inputs, hidden, SR, SI, SN,
                         Wir, bir, Wii, bii, Win, binw, out);
    {
        GArgs a;
        a.g[0].A = out + 9600; a.g[0].W = Wo1; a.g[0].wld = 256;
        a.g[0].bias = bo1; a.g[0].out = P1; a.g[0].outld = 256;
        a.g[0].outcol = 0; a.g[0].act = 1;
        kg_mma<<<dim3(13, 2, 1), 256>>>(a, NBV);
        a.g[0].A = P1; a.g[0].W = Wo2; a.g[0].bias = bo2; a.g[0].out = P2;
        kg_mma<<<dim3(13, 2, 1), 256>>>(a, NBV);
    }
    kpred<<<50, 256>>>(inputs, P2, Wo3, bo3, out);
}

// round 10
// speedup vs baseline: 1.0061x; 1.0045x over previous
#include <cuda_runtime.h>
#include <cstdint>
#include <math.h>

#define BB 32
#define VV 50
#define EE 2450
#define NBV 1600

__device__ float g_P[(size_t)NBV * 1536];             // k1 out; later k4 scratch (5 x 409600)
__device__ float g_msg3[(size_t)3 * BB * EE * 256];   // per-type messages
__device__ float g_agg[(size_t)NBV * 256];

extern __shared__ char s_dyn[];

// ===================== helpers =====================
__device__ __forceinline__ float ftanh(float x) {
    float y; asm("tanh.approx.f32 %0, %1;" : "=f"(y) : "f"(x)); return y;
}
__device__ __forceinline__ uint32_t to_tf32(float x) {
    uint32_t u; asm("cvt.rna.tf32.f32 %0, %1;" : "=r"(u) : "f"(x)); return u;
}
__device__ __forceinline__ void mma1688(float d[4],
                                        uint32_t a0, uint32_t a1, uint32_t a2, uint32_t a3,
                                        uint32_t b0, uint32_t b1) {
    asm volatile(
        "mma.sync.aligned.m16n8k8.row.col.f32.tf32.tf32.f32 "
        "{%0,%1,%2,%3}, {%4,%5,%6,%7}, {%8,%9}, {%0,%1,%2,%3};"
        : "+f"(d[0]), "+f"(d[1]), "+f"(d[2]), "+f"(d[3])
        : "r"(a0), "r"(a1), "r"(a2), "r"(a3), "r"(b0), "r"(b1));
}
#define APAD 36

// ===================== K2: per-type tf32 message kernel =====================
// block = 128 edges x 256 cols x 1 type. grid (20, 32, 3). 8 warps 2m x 4n (warp 64x64).
#define K2_SMEM ((128 + 256) * APAD * 4 + (128 + 256) * 4)
__global__ void __launch_bounds__(256, 1)
k2_msg(const float* __restrict__ edges, const float* __restrict__ W2,
       const float* __restrict__ b2) {
    char* sm = s_dyn;
    uint32_t (*As)[APAD] = (uint32_t(*)[APAD])sm;                       // [128][36]
    uint32_t (*Bs)[APAD] = (uint32_t(*)[APAD])(sm + 128 * APAD * 4);    // [256][36]
    float* sEw = (float*)(sm + (128 + 256) * APAD * 4);                 // [128]
    float* sB2 = sEw + 128;                                             // [256]

    const int tid = threadIdx.x;
    const int wid = tid >> 5, lane = tid & 31;
    const int gid = lane >> 2, tig = lane & 3;
    const int wn = wid & 3, wm = wid >> 2;     // 2(m) x 4(n)
    const int e0 = blockIdx.x * 128;
    const int b  = blockIdx.y;
    const int t  = blockIdx.z;

    if (tid < 128) {
        int e = e0 + tid;
        sEw[tid] = (e < EE) ? edges[((size_t)b * EE + e) * 4 + 1 + t] : 0.f;
    }
    sB2[tid] = b2[t * 256 + tid];

    float acc[4][8][4];
#pragma unroll
    for (int mt = 0; mt < 4; mt++)
#pragma unroll
        for (int nt = 0; nt < 8; nt++)
#pragma unroll
            for (int c = 0; c < 4; c++) acc[mt][nt][c] = 0.f;

    const float* Pbase = g_P + (size_t)(t * 2) * 256;

    for (int kc = 0; kc < 256; kc += 32) {
        __syncthreads();   // frag loads of previous iter done
        // ---- A build: h1 = tanh(Pr + Ps) tf32, 128 x 32 ----
#pragma unroll
        for (int i = tid; i < 1024; i += 256) {
            int row = i >> 3, k0 = (i & 7) * 4;
            int e = e0 + row;
            uint4 u = {0u, 0u, 0u, 0u};
            if (e < EE) {
                int s = e / 49, j = e - s * 49;
                int vr = j + (j >= s);
                float4 pr = *(const float4*)(Pbase + (size_t)(b * VV + vr) * 1536 + kc + k0);
                float4 ps = *(const float4*)(Pbase + (size_t)(b * VV + s) * 1536 + 256 + kc + k0);
                u.x = to_tf32(ftanh(pr.x + ps.x));
                u.y = to_tf32(ftanh(pr.y + ps.y));
                u.z = to_tf32(ftanh(pr.z + ps.z));
                u.w = to_tf32(ftanh(pr.w + ps.w));
            }
            *(uint4*)&As[row][k0] = u;
        }
        // ---- B build: W2 slice tf32, 256 x 32 ----
#pragma unroll
        for (int i = tid; i < 2048; i += 256) {
            int n = i >> 3, k0 = (i & 7) * 4;
            float4 w = *(const float4*)(W2 + ((size_t)t * 256 + n) * 256 + kc + k0);
            uint4 u;
            u.x = to_tf32(w.x); u.y = to_tf32(w.y); u.z = to_tf32(w.z); u.w = to_tf32(w.w);
            *(uint4*)&Bs[n][k0] = u;
        }
        __syncthreads();
#pragma unroll
        for (int ks = 0; ks < 4; ks++) {
            int k = ks * 8;
            uint32_t a[4][4];
#pragma unroll
            for (int mt = 0; mt < 4; mt++) {
                int row = wm * 64 + mt * 16 + gid;
                a[mt][0] = As[row][k + tig];
                a[mt][1] = As[row + 8][k + tig];
                a[mt][2] = As[row][k + tig + 4];
                a[mt][3] = As[row + 8][k + tig + 4];
            }
#pragma unroll
            for (int nt = 0; nt < 8; nt++) {
                int n = wn * 64 + nt * 8 + gid;
                uint32_t b0 = Bs[n][k + tig];
                uint32_t b1 = Bs[n][k + tig + 4];
#pragma unroll
                for (int mt = 0; mt < 4; mt++)
                    mma1688(acc[mt][nt], a[mt][0], a[mt][1], a[mt][2], a[mt][3], b0, b1);
            }
        }
    }
    // ---- epilogue: msg = tanh(acc + b2) * ew, store to per-type buffer ----
    float* mout = g_msg3 + ((size_t)t * BB + b) * EE * 256;
#pragma unroll
    for (int mt = 0; mt < 4; mt++) {
        int rl = wm * 64 + mt * 16 + gid;
        int eA = e0 + rl, eB = eA + 8;
        float ewA = sEw[rl], ewB = sEw[rl + 8];
#pragma unroll
        for (int nt = 0; nt < 8; nt++) {
            int c0 = wn * 64 + nt * 8 + 2 * tig;
            float bb0 = sB2[c0], bb1 = sB2[c0 + 1];
            if (eA < EE)
                *(float2*)(mout + (size_t)eA * 256 + c0) =
                    make_float2(ftanh(acc[mt][nt][0] + bb0) * ewA,
                                ftanh(acc[mt][nt][1] + bb1) * ewA);
            if (eB < EE)
                *(float2*)(mout + (size_t)eB * 256 + c0) =
                    make_float2(ftanh(acc[mt][nt][2] + bb0) * ewB,
                                ftanh(acc[mt][nt][3] + bb1) * ewB);
        }
    }
}

// ===================== K3: aggregate over incoming edges + types =====================
__global__ void k3_agg() {
    const int bv = blockIdx.x;
    const int b = bv / VV, v = bv - b * VV;
    const int h = threadIdx.x;
    const size_t toff = (size_t)BB * EE * 256;
    const float* base = g_msg3 + (size_t)b * EE * 256;
    float s0 = 0.f, s1 = 0.f, s2 = 0.f;
    for (int snd = 0; snd < VV; ++snd) {
        if (snd == v) continue;
        int j = (v < snd) ? v : v - 1;
        size_t off = (size_t)(snd * 49 + j) * 256 + h;
        s0 += base[off];
        s1 += base[toff + off];
        s2 += base[2 * toff + off];
    }
    g_agg[(size_t)bv * 256 + h] = (s0 + s1 + s2) * (1.f / 147.f);
}

// ===================== generic tf32 mma GEMM: C = act(A @ W^T + bias) =====================
// block tile 128 x 128, 8 warps 2m x 4n (warp 64 x 32). per-z args.
struct GArg {
    const float* A;        // [M, 256]
    const float* W;        // rows at stride wld
    const float* bias;     // [128*gridDim.y] or null
    float* out;
    int wld, outld, outcol, act;
};
struct GArgs { GArg g[6]; };

__global__ void __launch_bounds__(256, 2)
kg_mma(GArgs args, int M) {
    __shared__ uint32_t As[128][APAD];
    __shared__ uint32_t Bs[128][APAD];
    const GArg ga = args.g[blockIdx.z];
    const int tid = threadIdx.x;
    const int wid = tid >> 5, lane = tid & 31;
    const int gid = lane >> 2, tig = lane & 3;
    const int wn = wid & 3, wm = wid >> 2;     // 2(m) x 4(n), warp 64x32
    const int row0 = blockIdx.x * 128;
    const int col0 = blockIdx.y * 128;

    float acc[4][4][4];
#pragma unroll
    for (int mt = 0; mt < 4; mt++)
#pragma unroll
        for (int nt = 0; nt < 4; nt++)
#pragma unroll
            for (int c = 0; c < 4; c++) acc[mt][nt][c] = 0.f;

    for (int kc = 0; kc < 256; kc += 32) {
        __syncthreads();
#pragma unroll
        for (int i = tid; i < 1024; i += 256) {
            int r = i >> 3, k0 = (i & 7) * 4;
            int row = row0 + r;
            uint4 u = {0u, 0u, 0u, 0u};
            if (row < M) {
                float4 a = *(const float4*)(ga.A + (size_t)row * 256 + kc + k0);
                u.x = to_tf32(a.x); u.y = to_tf32(a.y); u.z = to_tf32(a.z); u.w = to_tf32(a.w);
            }
            *(uint4*)&As[r][k0] = u;
        }
#pragma unroll
        for (int i = tid; i < 1024; i += 256) {
            int n = i >> 3, k0 = (i & 7) * 4;
            float4 w = *(const float4*)(ga.W + (size_t)(col0 + n) * ga.wld + kc + k0);
            uint4 u;
            u.x = to_tf32(w.x); u.y = to_tf32(w.y); u.z = to_tf32(w.z); u.w = to_tf32(w.w);
            *(uint4*)&Bs[n][k0] = u;
        }
        __syncthreads();
#pragma unroll
        for (int ks = 0; ks < 4; ks++) {
            int k = ks * 8;
            uint32_t a[4][4];
#pragma unroll
            for (int mt = 0; mt < 4; mt++) {
                int row = wm * 64 + mt * 16 + gid;
                a[mt][0] = As[row][k + tig];
                a[mt][1] = As[row + 8][k + tig];
                a[mt][2] = As[row][k + tig + 4];
                a[mt][3] = As[row + 8][k + tig + 4];
            }
#pragma unroll
            for (int nt = 0; nt < 4; nt++) {
                int n = wn * 32 + nt * 8 + gid;
                uint32_t b0 = Bs[n][k + tig];
                uint32_t b1 = Bs[n][k + tig + 4];
#pragma unroll
                for (int mt = 0; mt < 4; mt++)
                    mma1688(acc[mt][nt], a[mt][0], a[mt][1], a[mt][2], a[mt][3], b0, b1);
            }
        }
    }
#pragma unroll
    for (int mt = 0; mt < 4; mt++) {
        int rl = wm * 64 + mt * 16 + gid;
        int rA = row0 + rl, rB = rA + 8;
#pragma unroll
        for (int nt = 0; nt < 4; nt++) {
            int c0 = wn * 32 + nt * 8 + 2 * tig;
            float bb0 = 0.f, bb1 = 0.f;
            if (ga.bias) { bb0 = ga.bias[col0 + c0]; bb1 = ga.bias[col0 + c0 + 1]; }
            float v0 = acc[mt][nt][0] + bb0, v1 = acc[mt][nt][1] + bb1;
            float v2 = acc[mt][nt][2] + bb0, v3 = acc[mt][nt][3] + bb1;
            if (ga.act) {
                v0 = fmaxf(v0, 0.f); v1 = fmaxf(v1, 0.f);
                v2 = fmaxf(v2, 0.f); v3 = fmaxf(v3, 0.f);
            }
            int gc = ga.outcol + col0 + c0;
            if (rA < M) *(float2*)(ga.out + (size_t)rA * ga.outld + gc) = make_float2(v0, v1);
            if (rB < M) *(float2*)(ga.out + (size_t)rB * ga.outld + gc) = make_float2(v2, v3);
        }
    }
}

// ===================== gates =====================
__global__ void kgate(const float* __restrict__ inputs, const float* __restrict__ hidden,
                      const float* __restrict__ SR, const float* __restrict__ SI,
                      const float* __restrict__ SN,
                      const float* __restrict__ Wir, const float* __restrict__ bir,
                      const float* __restrict__ Wii, const float* __restrict__ bii,
                      const float* __restrict__ Win, const float* __restrict__ binw,
                      float* __restrict__ out) {
    const int row = blockIdx.x, col = threadIdx.x;
    __shared__ float x[6];
    if (col < 6) x[col] = inputs[row * 6 + col];
    __syncthreads();
    float xr = bir[col], xi = bii[col], xn = binw[col];
#pragma unroll
    for (int d = 0; d < 6; d++) {
        float xd = x[d];
        xr += Wir[col*6+d] * xd; xi += Wii[col*6+d] * xd; xn += Win[col*6+d] * xd;
    }
    size_t idx = (size_t)row * 256 + col;
    float rg = 1.f / (1.f + expf(-(SR[idx] + xr)));
    float ig = 1.f / (1.f + expf(-(SI[idx] + xi)));
    float ng = tanhf(xn + rg * SN[idx]);
    out[9600 + idx] = (1.f - ig) * ng + ig * hidden[idx];
}

// ===================== prediction =====================
__global__ void kpred(const float* __restrict__ inputs, const float* __restrict__ p2,
                      const float* __restrict__ Wo3, const float* __restrict__ bo3,
                      float* __restrict__ out) {
    __shared__ float sP[32 * 257];
    __shared__ float sW3[6 * 256];
    const int tid = threadIdx.x;
    const int row0 = blockIdx.x * 32;
    for (int i = tid; i < 32 * 256; i += 256) {
        int r = i >> 8, k = i & 255;
        sP[r * 257 + k] = p2[(size_t)(row0 + r) * 256 + k];
    }
    for (int i = tid; i < 1536; i += 256) sW3[i] = Wo3[i];
    __syncthreads();
    if (tid < 192) {
        int row = tid / 6, d = tid - (tid / 6) * 6;
        float s = bo3[d];
        for (int k = 0; k < 256; k++) s += sP[row * 257 + k] * sW3[d * 256 + k];
        size_t g = (size_t)(row0 + row) * 6 + d;
        out[g] = inputs[g] + s;
    }
}

// ===================== launch =====================
extern "C" void kernel_launch(void* const* d_in, const int* in_sizes, int n_in,
                              void* d_out, int out_size) {
    const float* inputs = (const float*)d_in[0];
    const float* hidden = (const float*)d_in[1];
    const float* edges  = (const float*)d_in[2];
    const float* W1     = (const float*)d_in[3];
    const float* b1     = (const float*)d_in[4];
    const float* W2     = (const float*)d_in[5];
    const float* b2     = (const float*)d_in[6];
    const float* Whr    = (const float*)d_in[7];
    const float* Whi    = (const float*)d_in[8];
    const float* Whh    = (const float*)d_in[9];
    const float* Wir    = (const float*)d_in[10];
    const float* bir    = (const float*)d_in[11];
    const float* Wii    = (const float*)d_in[12];
    const float* bii    = (const float*)d_in[13];
    const float* Win    = (const float*)d_in[14];
    const float* binw   = (const float*)d_in[15];
    const float* Wo1    = (const float*)d_in[16];
    const float* bo1    = (const float*)d_in[17];
    const float* Wo2    = (const float*)d_in[18];
    const float* bo2    = (const float*)d_in[19];
    const float* Wo3    = (const float*)d_in[20];
    const float* bo3    = (const float*)d_in[21];
    float* out = (float*)d_out;

    void* pP = nullptr; void* pAgg = nullptr;
    cudaGetSymbolAddress(&pP, g_P);
    cudaGetSymbolAddress(&pAgg, g_agg);
    float* gp = (float*)pP;
    float* gagg = (float*)pAgg;
    float* SR = gp;                 // g_P reused as scratch after k2 consumes it
    float* SI = gp + 409600;
    float* SN = gp + 819200;
    float* P1 = gp + 1228800;
    float* P2 = gp + 1638400;

    cudaFuncSetAttribute(k2_msg, cudaFuncAttributeMaxDynamicSharedMemorySize, K2_SMEM);

    // K1: node projections via mma, z -> (t, dir)
    {
        GArgs a;
        for (int z = 0; z < 6; z++) {
            int t = z >> 1, dir = z & 1;
            a.g[z].A = hidden;
            a.g[z].W = W1 + (size_t)t * 256 * 512 + dir * 256;
            a.g[z].wld = 512;
            a.g[z].bias = (dir == 0) ? (b1 + t * 256) : nullptr;
            a.g[z].out = gp;
            a.g[z].outld = 1536;
            a.g[z].outcol = (t * 2 + dir) * 256;
            a.g[z].act = 0;
        }
        kg_mma<<<dim3(13, 2, 6), 256>>>(a, NBV);
    }
    k2_msg<<<dim3(20, 32, 3), 256, K2_SMEM>>>(edges, W2, b2);
    k3_agg<<<1600, 256>>>();
    // R, I, N
    {
        GArgs a;
        const float* Ws[3] = {Whr, Whi, Whh};
        float* Os[3] = {SR, SI, SN};
        for (int z = 0; z < 3; z++) {
            a.g[z].A = gagg; a.g[z].W = Ws[z]; a.g[z].wld = 256;
            a.g[z].bias = nullptr; a.g[z].out = Os[z];
            a.g[z].outld = 256; a.g[z].outcol = 0; a.g[z].act = 0;
        }
        kg_mma<<<dim3(13, 2, 3), 256>>>(a, NBV);
    }
    kgate<<<1600, 256>>>(inputs, hidden, SR, SI, SN,
                         Wir, bir, Wii, bii, Win, binw, out);
    {
        GArgs a;
        a.g[0].A = out + 9600; a.g[0].W = Wo1; a.g[0].wld = 256;
        a.g[0].bias = bo1; a.g[0].out = P1; a.g[0].outld = 256;
        a.g[0].outcol = 0; a.g[0].act = 1;
        kg_mma<<<dim3(13, 2, 1), 256>>>(a, NBV);
        a.g[0].A = P1; a.g[0].W = Wo2; a.g[0].bias = bo2; a.g[0].out = P2;
        kg_mma<<<dim3(13, 2, 1), 256>>>(a, NBV);
    }
    kpred<<<50, 256>>>(inputs, P2, Wo3, bo3, out);
}

// round 11
// speedup vs baseline: 1.0921x; 1.0854x over previous
#include <cuda_runtime.h>
#include <cstdint>
#include <math.h>

#define BB 32
#define VV 50
#define EE 2450
#define NBV 1600

__device__ float g_P[(size_t)NBV * 1536];             // k1 out; later k4 scratch (5 x 409600)
__device__ float g_agg3[(size_t)3 * NBV * 256];       // per-type partial aggregates
__device__ float g_agg[(size_t)NBV * 256];

extern __shared__ char s_dyn[];

// ===================== helpers =====================
__device__ __forceinline__ float ftanh(float x) {
    float y; asm("tanh.approx.f32 %0, %1;" : "=f"(y) : "f"(x)); return y;
}
__device__ __forceinline__ uint32_t to_tf32(float x) {
    uint32_t u; asm("cvt.rna.tf32.f32 %0, %1;" : "=r"(u) : "f"(x)); return u;
}
__device__ __forceinline__ void mma1688(float d[4],
                                        uint32_t a0, uint32_t a1, uint32_t a2, uint32_t a3,
                                        uint32_t b0, uint32_t b1) {
    asm volatile(
        "mma.sync.aligned.m16n8k8.row.col.f32.tf32.tf32.f32 "
        "{%0,%1,%2,%3}, {%4,%5,%6,%7}, {%8,%9}, {%0,%1,%2,%3};"
        : "+f"(d[0]), "+f"(d[1]), "+f"(d[2]), "+f"(d[3])
        : "r"(a0), "r"(a1), "r"(a2), "r"(a3), "r"(b0), "r"(b1));
}
#define APAD 36

// ===================== K2: receiver-major tf32 message kernel + fused aggregation ====
// block = 2 receivers x 64 edge-rows (49 valid) x 256 cols x 1 type. grid (25, 32, 3).
// 8 warps 2m x 4n (warp tile 64x64).
// smem: As[128][36] | Bs[256][36] | sEw[128] | sB2[256] | stage[128][129]
#define OFF_BS   (128 * APAD * 4)
#define OFF_EW   (OFF_BS + 256 * APAD * 4)
#define OFF_B2   (OFF_EW + 128 * 4)
#define OFF_STG  (OFF_B2 + 256 * 4)
#define K2_SMEM  (OFF_STG + 128 * 129 * 4)

__global__ void __launch_bounds__(256, 1)
k2_msg(const float* __restrict__ edges, const float* __restrict__ W2,
       const float* __restrict__ b2) {
    char* sm = s_dyn;
    uint32_t (*As)[APAD] = (uint32_t(*)[APAD])sm;                 // [128][36]
    uint32_t (*Bs)[APAD] = (uint32_t(*)[APAD])(sm + OFF_BS);      // [256][36]
    float* sEw  = (float*)(sm + OFF_EW);                          // [128]
    float* sB2  = (float*)(sm + OFF_B2);                          // [256]
    float* stage = (float*)(sm + OFF_STG);                        // [128][129]

    const int tid = threadIdx.x;
    const int wid = tid >> 5, lane = tid & 31;
    const int gid = lane >> 2, tig = lane & 3;
    const int wn = wid & 3, wm = wid >> 2;     // 2(m) x 4(n)
    const int v0 = blockIdx.x * 2;             // receiver pair
    const int b  = blockIdx.y;
    const int t  = blockIdx.z;

    // edge weights per row (pre-scaled by 1/147; pads -> 0)
    if (tid < 128) {
        int grp = tid >> 6, er = tid & 63;
        int v = v0 + grp;
        float w = 0.f;
        if (er < 49) {
            int s = er + (er >= v);
            int e = 49 * s + ((v < s) ? v : v - 1);
            w = edges[((size_t)b * EE + e) * 4 + 1 + t] * (1.f / 147.f);
        }
        sEw[tid] = w;
    }
    sB2[tid] = b2[t * 256 + tid];

    float acc[4][8][4];
#pragma unroll
    for (int mt = 0; mt < 4; mt++)
#pragma unroll
        for (int nt = 0; nt < 8; nt++)
#pragma unroll
            for (int c = 0; c < 4; c++) acc[mt][nt][c] = 0.f;

    const float* Pbase = g_P + (size_t)t * 512;   // [(bv)*1536 + dir*256 + h]

    for (int kc = 0; kc < 256; kc += 32) {
        __syncthreads();
        // ---- A build: rows 0..63 recv v0, 64..127 recv v0+1; h1 = tanh(Pr + Ps) ----
#pragma unroll
        for (int i = tid; i < 1024; i += 256) {
            int row = i >> 3, k0 = (i & 7) * 4;
            int grp = row >> 6, er = row & 63;
            int v = v0 + grp;
            uint4 u = {0u, 0u, 0u, 0u};
            if (er < 49) {
                int s = er + (er >= v);
                float4 pr = *(const float4*)(Pbase + (size_t)(b * VV + v) * 1536 + kc + k0);
                float4 ps = *(const float4*)(Pbase + (size_t)(b * VV + s) * 1536 + 256 + kc + k0);
                u.x = to_tf32(ftanh(pr.x + ps.x));
                u.y = to_tf32(ftanh(pr.y + ps.y));
                u.z = to_tf32(ftanh(pr.z + ps.z));
                u.w = to_tf32(ftanh(pr.w + ps.w));
            }
            *(uint4*)&As[row][k0] = u;
        }
        // ---- B build: W2 slice tf32, 256 x 32 ----
#pragma unroll
        for (int i = tid; i < 2048; i += 256) {
            int n = i >> 3, k0 = (i & 7) * 4;
            float4 w = *(const float4*)(W2 + ((size_t)t * 256 + n) * 256 + kc + k0);
            uint4 u;
            u.x = to_tf32(w.x); u.y = to_tf32(w.y); u.z = to_tf32(w.z); u.w = to_tf32(w.w);
            *(uint4*)&Bs[n][k0] = u;
        }
        __syncthreads();
#pragma unroll
        for (int ks = 0; ks < 4; ks++) {
            int k = ks * 8;
            uint32_t a[4][4];
#pragma unroll
            for (int mt = 0; mt < 4; mt++) {
                int row = wm * 64 + mt * 16 + gid;
                a[mt][0] = As[row][k + tig];
                a[mt][1] = As[row + 8][k + tig];
                a[mt][2] = As[row][k + tig + 4];
                a[mt][3] = As[row + 8][k + tig + 4];
            }
#pragma unroll
            for (int nt = 0; nt < 8; nt++) {
                int n = wn * 64 + nt * 8 + gid;
                uint32_t b0 = Bs[n][k + tig];
                uint32_t b1 = Bs[n][k + tig + 4];
#pragma unroll
                for (int mt = 0; mt < 4; mt++)
                    mma1688(acc[mt][nt], a[mt][0], a[mt][1], a[mt][2], a[mt][3], b0, b1);
            }
        }
    }

    // ---- fused epilogue: msg = tanh(acc+b2)*ew, local 49-row reduce, store partials ----
    for (int ch = 0; ch < 2; ch++) {     // column halves (128 cols each)
        __syncthreads();
        if ((wn >> 1) == ch) {
#pragma unroll
            for (int mt = 0; mt < 4; mt++) {
                int rl = wm * 64 + mt * 16 + gid;
                float ewA = sEw[rl], ewB = sEw[rl + 8];
#pragma unroll
                for (int nt = 0; nt < 8; nt++) {
                    int gc = wn * 64 + nt * 8 + 2 * tig;
                    int c0 = gc - ch * 128;
                    float bb0 = sB2[gc], bb1 = sB2[gc + 1];
                    stage[rl * 129 + c0]           = ftanh(acc[mt][nt][0] + bb0) * ewA;
                    stage[rl * 129 + c0 + 1]       = ftanh(acc[mt][nt][1] + bb1) * ewA;
                    stage[(rl + 8) * 129 + c0]     = ftanh(acc[mt][nt][2] + bb0) * ewB;
                    stage[(rl + 8) * 129 + c0 + 1] = ftanh(acc[mt][nt][3] + bb1) * ewB;
                }
            }
        }
        __syncthreads();
        int half = tid >> 7, col = tid & 127;
        float ssum = 0.f;
#pragma unroll
        for (int e2 = 0; e2 < 49; e2++)
            ssum += stage[(half * 64 + e2) * 129 + col];
        g_agg3[((size_t)t * NBV + b * VV + v0 + half) * 256 + ch * 128 + col] = ssum;
    }
}

// ===================== ksum: combine the 3 type partials =====================
__global__ void ksum() {
    size_t i = (size_t)blockIdx.x * 256 + threadIdx.x;
    const size_t n = (size_t)NBV * 256;
    g_agg[i] = g_agg3[i] + g_agg3[n + i] + g_agg3[2 * n + i];
}

// ===================== generic tf32 mma GEMM: C = act(A @ W^T + bias) =====================
struct GArg {
    const float* A;
    const float* W;
    const float* bias;
    float* out;
    int wld, outld, outcol, act;
};
struct GArgs { GArg g[6]; };

__global__ void __launch_bounds__(256, 2)
kg_mma(GArgs args, int M) {
    __shared__ uint32_t As[128][APAD];
    __shared__ uint32_t Bs[128][APAD];
    const GArg ga = args.g[blockIdx.z];
    const int tid = threadIdx.x;
    const int wid = tid >> 5, lane = tid & 31;
    const int gid = lane >> 2, tig = lane & 3;
    const int wn = wid & 3, wm = wid >> 2;
    const int row0 = blockIdx.x * 128;
    const int col0 = blockIdx.y * 128;

    float acc[4][4][4];
#pragma unroll
    for (int mt = 0; mt < 4; mt++)
#pragma unroll
        for (int nt = 0; nt < 4; nt++)
#pragma unroll
            for (int c = 0; c < 4; c++) acc[mt][nt][c] = 0.f;

    for (int kc = 0; kc < 256; kc += 32) {
        __syncthreads();
#pragma unroll
        for (int i = tid; i < 1024; i += 256) {
            int r = i >> 3, k0 = (i & 7) * 4;
            int row = row0 + r;
            uint4 u = {0u, 0u, 0u, 0u};
            if (row < M) {
                float4 a = *(const float4*)(ga.A + (size_t)row * 256 + kc + k0);
                u.x = to_tf32(a.x); u.y = to_tf32(a.y); u.z = to_tf32(a.z); u.w = to_tf32(a.w);
            }
            *(uint4*)&As[r][k0] = u;
        }
#pragma unroll
        for (int i = tid; i < 1024; i += 256) {
            int n = i >> 3, k0 = (i & 7) * 4;
            float4 w = *(const float4*)(ga.W + (size_t)(col0 + n) * ga.wld + kc + k0);
            uint4 u;
            u.x = to_tf32(w.x); u.y = to_tf32(w.y); u.z = to_tf32(w.z); u.w = to_tf32(w.w);
            *(uint4*)&Bs[n][k0] = u;
        }
        __syncthreads();
#pragma unroll
        for (int ks = 0; ks < 4; ks++) {
            int k = ks * 8;
            uint32_t a[4][4];
#pragma unroll
            for (int mt = 0; mt < 4; mt++) {
                int row = wm * 64 + mt * 16 + gid;
                a[mt][0] = As[row][k + tig];
                a[mt][1] = As[row + 8][k + tig];
                a[mt][2] = As[row][k + tig + 4];
                a[mt][3] = As[row + 8][k + tig + 4];
            }
#pragma unroll
            for (int nt = 0; nt < 4; nt++) {
                int n = wn * 32 + nt * 8 + gid;
                uint32_t b0 = Bs[n][k + tig];
                uint32_t b1 = Bs[n][k + tig + 4];
#pragma unroll
                for (int mt = 0; mt < 4; mt++)
                    mma1688(acc[mt][nt], a[mt][0], a[mt][1], a[mt][2], a[mt][3], b0, b1);
            }
        }
    }
#pragma unroll
    for (int mt = 0; mt < 4; mt++) {
        int rl = wm * 64 + mt * 16 + gid;
        int rA = row0 + rl, rB = rA + 8;
#pragma unroll
        for (int nt = 0; nt < 4; nt++) {
            int c0 = wn * 32 + nt * 8 + 2 * tig;
            float bb0 = 0.f, bb1 = 0.f;
            if (ga.bias) { bb0 = ga.bias[col0 + c0]; bb1 = ga.bias[col0 + c0 + 1]; }
            float v0 = acc[mt][nt][0] + bb0, v1 = acc[mt][nt][1] + bb1;
            float v2 = acc[mt][nt][2] + bb0, v3 = acc[mt][nt][3] + bb1;
            if (ga.act) {
                v0 = fmaxf(v0, 0.f); v1 = fmaxf(v1, 0.f);
                v2 = fmaxf(v2, 0.f); v3 = fmaxf(v3, 0.f);
            }
            int gc = ga.outcol + col0 + c0;
            if (rA < M) *(float2*)(ga.out + (size_t)rA * ga.outld + gc) = make_float2(v0, v1);
            if (rB < M) *(float2*)(ga.out + (size_t)rB * ga.outld + gc) = make_float2(v2, v3);
        }
    }
}

// ===================== gates =====================
__global__ void kgate(const float* __restrict__ inputs, const float* __restrict__ hidden,
                      const float* __restrict__ SR, const float* __restrict__ SI,
                      const float* __restrict__ SN,
                      const float* __restrict__ Wir, const float* __restrict__ bir,
                      const float* __restrict__ Wii, const float* __restrict__ bii,
                      const float* __restrict__ Win, const float* __restrict__ binw,
                      float* __restrict__ out) {
    const int row = blockIdx.x, col = threadIdx.x;
    __shared__ float x[6];
    if (col < 6) x[col] = inputs[row * 6 + col];
    __syncthreads();
    float xr = bir[col], xi = bii[col], xn = binw[col];
#pragma unroll
    for (int d = 0; d < 6; d++) {
        float xd = x[d];
        xr += Wir[col*6+d] * xd; xi += Wii[col*6+d] * xd; xn += Win[col*6+d] * xd;
    }
    size_t idx = (size_t)row * 256 + col;
    float rg = 1.f / (1.f + expf(-(SR[idx] + xr)));
    float ig = 1.f / (1.f + expf(-(SI[idx] + xi)));
    float ng = tanhf(xn + rg * SN[idx]);
    out[9600 + idx] = (1.f - ig) * ng + ig * hidden[idx];
}

// ===================== prediction =====================
__global__ void kpred(const float* __restrict__ inputs, const float* __restrict__ p2,
                      const float* __restrict__ Wo3, const float* __restrict__ bo3,
                      float* __restrict__ out) {
    __shared__ float sP[32 * 257];
    __shared__ float sW3[6 * 256];
    const int tid = threadIdx.x;
    const int row0 = blockIdx.x * 32;
    for (int i = tid; i < 32 * 256; i += 256) {
        int r = i >> 8, k = i & 255;
        sP[r * 257 + k] = p2[(size_t)(row0 + r) * 256 + k];
    }
    for (int i = tid; i < 1536; i += 256) sW3[i] = Wo3[i];
    __syncthreads();
    if (tid < 192) {
        int row = tid / 6, d = tid - (tid / 6) * 6;
        float s = bo3[d];
        for (int k = 0; k < 256; k++) s += sP[row * 257 + k] * sW3[d * 256 + k];
        size_t g = (size_t)(row0 + row) * 6 + d;
        out[g] = inputs[g] + s;
    }
}

// ===================== launch =====================
extern "C" void kernel_launch(void* const* d_in, const int* in_sizes, int n_in,
                              void* d_out, int out_size) {
    const float* inputs = (const float*)d_in[0];
    const float* hidden = (const float*)d_in[1];
    const float* edges  = (const float*)d_in[2];
    const float* W1     = (const float*)d_in[3];
    const float* b1     = (const float*)d_in[4];
    const float* W2     = (const float*)d_in[5];
    const float* b2     = (const float*)d_in[6];
    const float* Whr    = (const float*)d_in[7];
    const float* Whi    = (const float*)d_in[8];
    const float* Whh    = (const float*)d_in[9];
    const float* Wir    = (const float*)d_in[10];
    const float* bir    = (const float*)d_in[11];
    const float* Wii    = (const float*)d_in[12];
    const float* bii    = (const float*)d_in[13];
    const float* Win    = (const float*)d_in[14];
    const float* binw   = (const float*)d_in[15];
    const float* Wo1    = (const float*)d_in[16];
    const float* bo1    = (const float*)d_in[17];
    const float* Wo2    = (const float*)d_in[18];
    const float* bo2    = (const float*)d_in[19];
    const float* Wo3    = (const float*)d_in[20];
    const float* bo3    = (const float*)d_in[21];
    float* out = (float*)d_out;

    void* pP = nullptr; void* pAgg = nullptr;
    cudaGetSymbolAddress(&pP, g_P);
    cudaGetSymbolAddress(&pAgg, g_agg);
    float* gp = (float*)pP;
    float* gagg = (float*)pAgg;
    float* SR = gp;                 // g_P reused as scratch after k2 consumes it
    float* SI = gp + 409600;
    float* SN = gp + 819200;
    float* P1 = gp + 1228800;
    float* P2 = gp + 1638400;

    cudaFuncSetAttribute(k2_msg, cudaFuncAttributeMaxDynamicSharedMemorySize, K2_SMEM);

    // K1: node projections via mma, z -> (t, dir)
    {
        GArgs a;
        for (int z = 0; z < 6; z++) {
            int t = z >> 1, dir = z & 1;
            a.g[z].A = hidden;
            a.g[z].W = W1 + (size_t)t * 256 * 512 + dir * 256;
            a.g[z].wld = 512;
            a.g[z].bias = (dir == 0) ? (b1 + t * 256) : nullptr;
            a.g[z].out = gp;
            a.g[z].outld = 1536;
            a.g[z].outcol = (t * 2 + dir) * 256;
            a.g[z].act = 0;
        }
        kg_mma<<<dim3(13, 2, 6), 256>>>(a, NBV);
    }
    k2_msg<<<dim3(25, 32, 3), 256, K2_SMEM>>>(edges, W2, b2);
    ksum<<<1600, 256>>>();
    // R, I, N
    {
        GArgs a;
        const float* Ws[3] = {Whr, Whi, Whh};
        float* Os[3] = {SR, SI, SN};
        for (int z = 0; z < 3; z++) {
            a.g[z].A = gagg; a.g[z].W = Ws[z]; a.g[z].wld = 256;
            a.g[z].bias = nullptr; a.g[z].out = Os[z];
            a.g[z].outld = 256; a.g[z].outcol = 0; a.g[z].act = 0;
        }
        kg_mma<<<dim3(13, 2, 3), 256>>>(a, NBV);
    }
    kgate<<<1600, 256>>>(inputs, hidden, SR, SI, SN,
                         Wir, bir, Wii, bii, Win, binw, out);
    {
        GArgs a;
        a.g[0].A = out + 9600; a.g[0].W = Wo1; a.g[0].wld = 256;
        a.g[0].bias = bo1; a.g[0].out = P1; a.g[0].outld = 256;
        a.g[0].outcol = 0; a.g[0].act = 1;
        kg_mma<<<dim3(13, 2, 1), 256>>>(a, NBV);
        a.g[0].A = P1; a.g[0].W = Wo2; a.g[0].bias = bo2; a.g[0].out = P2;
        kg_mma<<<dim3(13, 2, 1), 256>>>(a, NBV);
    }
    kpred<<<50, 256>>>(inputs, P2, Wo3, bo3, out);
}